// round 8
// baseline (speedup 1.0000x reference)
#include <cuda_runtime.h>
#include <math.h>

// ---------------------------------------------------------------------------
// Problem constants
// ---------------------------------------------------------------------------
#define W_IN   3840
#define H_IN   2160
#define NCH    3
#define HMSZ   256      // HM
#define MSZ    64       // mask size
#define KMAX   256
#define NCLS   7
#define FILLV  (-1000000)

// Output section offsets (float32 concatenation of the reference tuple)
#define OFF_HEAT    0
#define OFF_COORDS  (HMSZ*HMSZ)                 // 65536
#define OFF_SURV    (OFF_COORDS + KMAX*2)       // 66048
#define OFF_LOGITS  (OFF_SURV + KMAX)           // 66304
#define OFF_LABELS  (OFF_LOGITS + KMAX*NCLS)    // 68096

// ---------------------------------------------------------------------------
// Scratch (static __device__ arrays — no allocations allowed)
// ---------------------------------------------------------------------------
__device__ float    g_A[NCH * H_IN * HMSZ];   // horizontal-resized to 256 cols
__device__ float    g_B[NCH * H_IN * MSZ];    // horizontal-resized to 64 cols
__device__ float    g_hx[NCH * HMSZ * HMSZ];  // h_x (3,256,256)
__device__ float    g_mx[NCH * MSZ * MSZ];    // m_x (3,64,64)
__device__ float    g_heat[HMSZ * HMSZ];      // heatmap
__device__ unsigned g_bits[2048];             // peak bitmask, pixel-ordered
__device__ int      g_ri[KMAX];
__device__ int      g_ci[KMAX];
__device__ int      g_surv[KMAX];

// ---------------------------------------------------------------------------
// K1: horizontal antialiased bilinear resize: x row (3840) -> 256 cols (A)
//     and 64 cols (B). One block per (row, channel). x is read exactly once.
// ---------------------------------------------------------------------------
__global__ __launch_bounds__(512) void hresize_kernel(const float* __restrict__ x) {
    const int row = blockIdx.x;
    const int ch  = blockIdx.y;
    __shared__ float srow[W_IN];

    const float4* src = (const float4*)(x + ((size_t)ch * H_IN + row) * W_IN);
    float4* s4 = (float4*)srow;
    for (int i = threadIdx.x; i < W_IN / 4; i += 512) s4[i] = src[i];
    __syncthreads();

    const int t = threadIdx.x;
    if (t < 256) {
        const float inv  = 15.0f;
        const float rinv = 1.0f / inv;
        float center = (t + 0.5f) * inv - 0.5f;
        int j0 = max(0, (int)ceilf(center - inv));
        int j1 = min(W_IN - 1, (int)floorf(center + inv));
        float sw = 0.f, sv = 0.f;
        for (int j = j0; j <= j1; ++j) {
            float w = fmaxf(0.f, 1.0f - fabsf(center - (float)j) * rinv);
            sw += w; sv += w * srow[j];
        }
        g_A[((size_t)ch * H_IN + row) * HMSZ + t] = sv / sw;
    } else {
        const int u = t - 256;
        const int o = u >> 2;          // output col 0..63
        const int q = u & 3;           // sub-lane 0..3
        const float inv  = 60.0f;
        const float rinv = 1.0f / inv;
        float center = (o + 0.5f) * inv - 0.5f;
        int j0 = max(0, (int)ceilf(center - inv));
        int j1 = min(W_IN - 1, (int)floorf(center + inv));
        float sw = 0.f, sv = 0.f;
        for (int j = j0 + q; j <= j1; j += 4) {
            float w = fmaxf(0.f, 1.0f - fabsf(center - (float)j) * rinv);
            sw += w; sv += w * srow[j];
        }
        sv += __shfl_xor_sync(0xffffffffu, sv, 1);
        sw += __shfl_xor_sync(0xffffffffu, sw, 1);
        sv += __shfl_xor_sync(0xffffffffu, sv, 2);
        sw += __shfl_xor_sync(0xffffffffu, sw, 2);
        if (q == 0)
            g_B[((size_t)ch * H_IN + row) * MSZ + o] = sv / sw;
    }
}

// ---------------------------------------------------------------------------
// K2: merged vertical resizes.
// ---------------------------------------------------------------------------
__global__ __launch_bounds__(256) void vresize_kernel() {
    const int ch = blockIdx.y;
    if (blockIdx.x < 256) {
        const int col  = threadIdx.x;
        const int rout = blockIdx.x;
        const float inv  = 8.4375f;     // 2160/256
        const float rinv = 1.0f / inv;
        float center = (rout + 0.5f) * inv - 0.5f;
        int j0 = max(0, (int)ceilf(center - inv));
        int j1 = min(H_IN - 1, (int)floorf(center + inv));
        const float* base = g_A + (size_t)ch * H_IN * HMSZ + col;
        float sw = 0.f, sv = 0.f;
        for (int j = j0; j <= j1; ++j) {
            float w = fmaxf(0.f, 1.0f - fabsf(center - (float)j) * rinv);
            sw += w; sv += w * base[(size_t)j * HMSZ];
        }
        g_hx[(ch * HMSZ + rout) * HMSZ + col] = sv / sw;
    } else {
        const int rout = blockIdx.x - 256;  // 0..63
        const int col  = threadIdx.x;
        if (col >= MSZ) return;
        const float inv  = 33.75f;      // 2160/64
        const float rinv = 1.0f / inv;
        float center = (rout + 0.5f) * inv - 0.5f;
        int j0 = max(0, (int)ceilf(center - inv));
        int j1 = min(H_IN - 1, (int)floorf(center + inv));
        const float* base = g_B + (size_t)ch * H_IN * MSZ + col;
        float sw = 0.f, sv = 0.f;
        for (int j = j0; j <= j1; ++j) {
            float w = fmaxf(0.f, 1.0f - fabsf(center - (float)j) * rinv);
            sw += w; sv += w * base[(size_t)j * MSZ];
        }
        g_mx[(ch * MSZ + rout) * MSZ + col] = sv / sw;
    }
}

// ---------------------------------------------------------------------------
// K3: heat row kernel with inline mask-row computation.
// ---------------------------------------------------------------------------
__global__ __launch_bounds__(256) void heat_kernel(const float* __restrict__ lw,
                                                   const float* __restrict__ lb,
                                                   const float* __restrict__ mw,
                                                   const float* __restrict__ mb,
                                                   float* __restrict__ out) {
    const int r = blockIdx.x;
    const int c = threadIdx.x;
    __shared__ float smk[MSZ];

    if (c < MSZ) {
        const int mr = r >> 2;
        float acc = mb[0];
        #pragma unroll
        for (int ch = 0; ch < NCH; ++ch) {
            #pragma unroll
            for (int kh = 0; kh < 3; ++kh) {
                int rr = mr + kh - 1;
                if (rr < 0 || rr >= MSZ) continue;
                #pragma unroll
                for (int kw = 0; kw < 3; ++kw) {
                    int cc = c + kw - 1;
                    if (cc < 0 || cc >= MSZ) continue;
                    acc += g_mx[(ch * MSZ + rr) * MSZ + cc] * mw[ch * 9 + kh * 3 + kw];
                }
            }
        }
        acc = fminf(fmaxf(acc, 0.0f), 1.0f);
        if (acc < 0.6f) acc = 0.0f;
        smk[c] = acc;
    }
    __syncthreads();

    float acc = lb[0];
    #pragma unroll
    for (int ch = 0; ch < NCH; ++ch) {
        #pragma unroll
        for (int kh = 0; kh < 3; ++kh) {
            int rr = r + kh - 1;
            if (rr < 0 || rr >= HMSZ) continue;
            #pragma unroll
            for (int kw = 0; kw < 3; ++kw) {
                int cc = c + kw - 1;
                if (cc < 0 || cc >= HMSZ) continue;
                acc += g_hx[(ch * HMSZ + rr) * HMSZ + cc] * lw[ch * 9 + kh * 3 + kw];
            }
        }
    }
    acc = fminf(fmaxf(acc, 0.0f), 1.0f);
    if (acc < 0.4f) acc = 0.0f;
    float h = acc * smk[c >> 2];
    g_heat[r * HMSZ + c] = h;
    out[OFF_HEAT + r * HMSZ + c] = h;
}

// ---------------------------------------------------------------------------
// K4a: grid-parallel peak bitmask. 64 blocks x 1024 threads, one pixel each.
//      Each warp writes one ballot word (pixel-ordered).
// ---------------------------------------------------------------------------
__global__ __launch_bounds__(1024) void peakbits_kernel() {
    const int idx = blockIdx.x * 1024 + threadIdx.x;
    const int r = idx >> 8, c = idx & 255;
    float v  = g_heat[idx];
    float rt = (c < 255) ? g_heat[idx + 1]   : 0.f;
    float lf = (c > 0)   ? g_heat[idx - 1]   : 0.f;
    float dn = (r < 255) ? g_heat[idx + 256] : 0.f;
    float up = (r > 0)   ? g_heat[idx - 256] : 0.f;
    bool pk = (v > rt) && (v > lf) && (v > dn) && (v > up);
    unsigned bal = __ballot_sync(0xffffffffu, pk);
    if ((threadIdx.x & 31) == 0) g_bits[idx >> 5] = bal;
}

// ---------------------------------------------------------------------------
// K4b: ordered compaction + survive, one block of 256 threads.
//      Thread t owns 8 bitmask words = heatmap row t.
// ---------------------------------------------------------------------------
__global__ __launch_bounds__(256) void finish_kernel(float* __restrict__ out) {
    __shared__ int s_wsum[8];
    __shared__ float sr[KMAX], sc[KMAX];
    __shared__ int   sval[KMAX];

    const int tid  = threadIdx.x;
    const int lane = tid & 31;
    const int warp = tid >> 5;

    unsigned w[8];
    int cnt = 0;
    #pragma unroll
    for (int i = 0; i < 8; ++i) {
        w[i] = g_bits[tid * 8 + i];
        cnt += __popc(w[i]);
    }

    // block exclusive scan (8 warps)
    int incl = cnt;
    #pragma unroll
    for (int d = 1; d < 32; d <<= 1) {
        int n = __shfl_up_sync(0xffffffffu, incl, d);
        if (lane >= d) incl += n;
    }
    if (lane == 31) s_wsum[warp] = incl;
    __syncthreads();
    if (tid == 0) {
        int run = 0;
        #pragma unroll
        for (int i = 0; i < 8; ++i) { run += s_wsum[i]; s_wsum[i] = run; }
    }
    __syncthreads();
    int slot  = incl - cnt + (warp ? s_wsum[warp - 1] : 0);
    int total = s_wsum[7];

    // ordered bit-scatter: thread t = row t, LSB-first = ascending col
    if (slot < KMAX && cnt) {
        #pragma unroll
        for (int i = 0; i < 8; ++i) {
            unsigned b = w[i];
            int base = tid * 256 + i * 32;
            while (b) {
                int bit = __ffs(b) - 1;
                b &= b - 1;
                if (slot < KMAX) {
                    int idx = base + bit;
                    g_ri[slot] = idx >> 8;
                    g_ci[slot] = idx & 255;
                }
                ++slot;
            }
        }
    }
    __syncthreads();
    if (tid >= total) { g_ri[tid] = FILLV; g_ci[tid] = FILLV; }
    __syncthreads();

    // survive
    {
        int rij = g_ri[tid], cij = g_ci[tid];
        sr[tid] = (float)rij; sc[tid] = (float)cij;
        sval[tid] = (rij > FILLV) ? 1 : 0;
        out[OFF_COORDS + 2 * tid]     = (float)rij;
        out[OFF_COORDS + 2 * tid + 1] = (float)cij;
    }
    __syncthreads();
    {
        float rj = sr[tid], cj = sc[tid];
        bool rej = false;
        #pragma unroll 4
        for (int i = 0; i < KMAX; ++i) {
            float dr = sr[i] - rj, dc = sc[i] - cj;
            float d2 = dr * dr + dc * dc;
            if (sval[i] && d2 > 1.0f && d2 < 9.0f) rej = true;
        }
        int s = (sval[tid] && !rej) ? 1 : 0;
        g_surv[tid] = s;
        out[OFF_SURV + tid] = (float)s;
    }
}

// ---------------------------------------------------------------------------
// K5: classify. survive==0 blocks early-out (logits exactly 0, label 0).
// ---------------------------------------------------------------------------
__global__ __launch_bounds__(256) void classify_kernel(const float* __restrict__ lw,
                                                       const float* __restrict__ lb,
                                                       float* __restrict__ out) {
    const int k = blockIdx.x;
    const int t = threadIdx.x;

    if (g_surv[k] == 0) {
        if (t < NCLS) out[OFF_LOGITS + k * NCLS + t] = 0.0f;
        if (t == 0)   out[OFF_LABELS + k] = 0.0f;
        return;
    }

    __shared__ float red[8 * NCLS];
    const int lane = t & 31;
    const int warp = t >> 5;

    int r0 = min(max(g_ri[k], 0), HMSZ - 1);
    int c0 = min(max(g_ci[k], 0), HMSZ - 1);

    float acc[NCLS];
    #pragma unroll
    for (int q = 0; q < NCLS; ++q) acc[q] = 0.f;

    for (int i = t; i < 3 * 32 * 32; i += 256) {
        int ch = i >> 10, rem = i & 1023;
        int wr = rem >> 5, wc = rem & 31;
        int gr = r0 + wr - 16, gc = c0 + wc - 16;
        float v = 0.f;
        if (gr >= 0 && gr < HMSZ && gc >= 0 && gc < HMSZ)
            v = g_hx[(ch << 16) + (gr << 8) + gc];
        const float* wrow = lw + (size_t)i * NCLS;
        #pragma unroll
        for (int q = 0; q < NCLS; ++q) acc[q] += v * wrow[q];
    }
    #pragma unroll
    for (int q = 0; q < NCLS; ++q) {
        #pragma unroll
        for (int off = 16; off; off >>= 1)
            acc[q] += __shfl_down_sync(0xffffffffu, acc[q], off);
    }
    if (lane == 0) {
        #pragma unroll
        for (int q = 0; q < NCLS; ++q) red[warp * NCLS + q] = acc[q];
    }
    __syncthreads();
    if (t == 0) {
        float z[NCLS];
        #pragma unroll
        for (int q = 0; q < NCLS; ++q) {
            float s = 0.f;
            #pragma unroll
            for (int w2 = 0; w2 < 8; ++w2) s += red[w2 * NCLS + q];
            z[q] = s + lb[q];
        }
        float m = z[0];
        #pragma unroll
        for (int q = 1; q < NCLS; ++q) m = fmaxf(m, z[q]);
        float se = 0.f;
        #pragma unroll
        for (int q = 0; q < NCLS; ++q) se += expf(z[q] - m);
        float lse = logf(se);
        float best = -1.0f; int bi = 0;
        #pragma unroll
        for (int q = 0; q < NCLS; ++q) {
            float lg = expf(z[q] - m - lse);
            out[OFF_LOGITS + k * NCLS + q] = lg;
            if (lg > best) { best = lg; bi = q; }
        }
        out[OFF_LABELS + k] = (float)bi;
    }
}

// ---------------------------------------------------------------------------
// Launch
// ---------------------------------------------------------------------------
extern "C" void kernel_launch(void* const* d_in, const int* in_sizes, int n_in,
                              void* d_out, int out_size) {
    const float* x       = (const float*)d_in[0];
    const float* loc_w   = (const float*)d_in[1];
    const float* loc_b   = (const float*)d_in[2];
    const float* mask_w  = (const float*)d_in[3];
    const float* mask_b  = (const float*)d_in[4];
    const float* label_w = (const float*)d_in[5];
    const float* label_b = (const float*)d_in[6];
    float* out = (float*)d_out;

    hresize_kernel<<<dim3(H_IN, NCH), 512>>>(x);
    vresize_kernel<<<dim3(HMSZ + MSZ, NCH), 256>>>();
    heat_kernel<<<HMSZ, 256>>>(loc_w, loc_b, mask_w, mask_b, out);
    peakbits_kernel<<<64, 1024>>>();
    finish_kernel<<<1, 256>>>(out);
    classify_kernel<<<KMAX, 256>>>(label_w, label_b, out);
}